// round 3
// baseline (speedup 1.0000x reference)
#include <cuda_runtime.h>
#include <cuda_fp16.h>

#define N_NODES 64000
#define N_GRAPHS 128
#define D 64
#define MAX_E 1024000

// ---------------- scratch (device globals; no allocation allowed) ----------
__device__ float  g_h0[N_NODES * D];
__device__ float  g_h1[N_NODES * D];
__device__ float  g_aggr[N_NODES * D];
__device__ __half g_xh[N_NODES * D];     // half gather tables (1 line/row)
__device__ __half g_hh0[N_NODES * D];
__device__ __half g_hh1[N_NODES * D];
__device__ float  g_y[N_NODES * 2];
__device__ int    g_deg[N_NODES];
__device__ int    g_rowptr[N_NODES + 1];
__device__ int    g_pos[N_NODES];
__device__ int    g_srcs[MAX_E];
__device__ float  g_inv[N_NODES];
__device__ float  g_pool[N_GRAPHS * 2];
__device__ int    g_gcnt[N_GRAPHS];
__device__ int    g_bsums[128];
__device__ int    g_is64;

__device__ __forceinline__ const float* sel_in(int s, const float* x) {
    return s == 0 ? x : (s == 1 ? g_h0 : g_h1);
}
__device__ __forceinline__ float* sel_out(int s) {
    return s == 1 ? g_h0 : g_h1;
}
__device__ __forceinline__ const __half2* sel_h(int s) {
    return (const __half2*)(s == 0 ? g_xh : (s == 1 ? g_hh0 : g_hh1));
}
__device__ __forceinline__ int load_idx(const void* p, int i) {
    return g_is64 ? (int)((const long long*)p)[i] : ((const int*)p)[i];
}

// ---------------- index dtype probe --------------------------------------
__global__ void k_detect(const void* edges) {
    if (threadIdx.x == 0 && blockIdx.x == 0) {
        const long long* p = (const long long*)edges;
        int ok = 1;
        for (int i = 0; i < 16; i++) {
            long long v = p[i];
            if (v < 0 || v >= N_NODES) ok = 0;
        }
        g_is64 = ok;
    }
}

__global__ void k_zero() {
    int i = blockIdx.x * blockDim.x + threadIdx.x;
    if (i < N_NODES) g_deg[i] = 0;
    if (i < N_GRAPHS * 2) g_pool[i] = 0.f;
    if (i < N_GRAPHS) g_gcnt[i] = 0;
}

// convert x (fp32) -> g_xh (half), 4 elems/thread
__global__ void k_tohalf(const float* __restrict__ x) {
    int i = blockIdx.x * blockDim.x + threadIdx.x;
    if (i >= N_NODES * D / 4) return;
    float4 v = ((const float4*)x)[i];
    __half2* o = (__half2*)g_xh;
    o[i * 2]     = __floats2half2_rn(v.x, v.y);
    o[i * 2 + 1] = __floats2half2_rn(v.z, v.w);
}

__global__ void k_count(const void* edges, int E) {
    int e = blockIdx.x * blockDim.x + threadIdx.x;
    if (e >= E) return;
    atomicAdd(&g_deg[load_idx(edges, E + e)], 1);
}

// ---------------- 3-kernel exclusive scan of degrees ----------------------
__global__ void k_scan1() {
    __shared__ int s[512];
    int t = threadIdx.x;
    int i = blockIdx.x * 512 + t;          // 125 blocks * 512 = 64000 exactly
    int d = g_deg[i];
    s[t] = d;
    __syncthreads();
    for (int off = 1; off < 512; off <<= 1) {
        int v = (t >= off) ? s[t - off] : 0;
        __syncthreads();
        s[t] += v;
        __syncthreads();
    }
    g_rowptr[i] = s[t] - d;
    if (t == 511) g_bsums[blockIdx.x] = s[511];
}

__global__ void k_scan2() {
    __shared__ int s[128];
    int t = threadIdx.x;
    int v = (t < 125) ? g_bsums[t] : 0;
    s[t] = v;
    __syncthreads();
    for (int off = 1; off < 128; off <<= 1) {
        int u = (t >= off) ? s[t - off] : 0;
        __syncthreads();
        s[t] += u;
        __syncthreads();
    }
    g_bsums[t] = s[t] - v;
}

// scan finalize + per-block graph-count histogram (batch sorted -> smem
// atomics absorb the same-address contention)
__global__ void k_scan3(int E, const void* __restrict__ batch) {
    __shared__ int h[N_GRAPHS];
    for (int i = threadIdx.x; i < N_GRAPHS; i += blockDim.x) h[i] = 0;
    __syncthreads();
    int t = threadIdx.x;
    int i = blockIdx.x * 512 + t;
    int rp = g_rowptr[i] + g_bsums[blockIdx.x];
    g_rowptr[i] = rp;
    g_pos[i] = rp;
    int d = g_deg[i];
    g_inv[i] = d > 0 ? 1.0f / (float)d : 0.f;
    if (i == 0) g_rowptr[N_NODES] = E;
    atomicAdd(&h[load_idx(batch, i)], 1);
    __syncthreads();
    for (int g = threadIdx.x; g < N_GRAPHS; g += blockDim.x)
        if (h[g]) atomicAdd(&g_gcnt[g], h[g]);
}

__global__ void k_fill(const void* edges, int E) {
    int e = blockIdx.x * blockDim.x + threadIdx.x;
    if (e >= E) return;
    int src = load_idx(edges, e);
    int dst = load_idx(edges, E + e);
    int pidx = atomicAdd(&g_pos[dst], 1);
    g_srcs[pidx] = src;
}

// ---------------- mean aggregation: warp per node, half2 lanes ------------
// Row = 64 halves = 128 B = ONE cache line per edge -> 1 L1tex wavefront.
__global__ void k_aggregate(int in_sel) {
    const __half2* __restrict__ in2 = sel_h(in_sel);
    int warp = (blockIdx.x * blockDim.x + threadIdx.x) >> 5;
    int lane = threadIdx.x & 31;
    if (warp >= N_NODES) return;
    int rs = g_rowptr[warp], re = g_rowptr[warp + 1];
    float2 acc = make_float2(0.f, 0.f);
    int e = rs;
    for (; e + 8 <= re; e += 8) {
        int s0 = g_srcs[e],     s1 = g_srcs[e + 1], s2 = g_srcs[e + 2], s3 = g_srcs[e + 3];
        int s4 = g_srcs[e + 4], s5 = g_srcs[e + 5], s6 = g_srcs[e + 6], s7 = g_srcs[e + 7];
        float2 v0 = __half22float2(in2[s0 * 32 + lane]);
        float2 v1 = __half22float2(in2[s1 * 32 + lane]);
        float2 v2 = __half22float2(in2[s2 * 32 + lane]);
        float2 v3 = __half22float2(in2[s3 * 32 + lane]);
        float2 v4 = __half22float2(in2[s4 * 32 + lane]);
        float2 v5 = __half22float2(in2[s5 * 32 + lane]);
        float2 v6 = __half22float2(in2[s6 * 32 + lane]);
        float2 v7 = __half22float2(in2[s7 * 32 + lane]);
        acc.x += ((v0.x + v1.x) + (v2.x + v3.x)) + ((v4.x + v5.x) + (v6.x + v7.x));
        acc.y += ((v0.y + v1.y) + (v2.y + v3.y)) + ((v4.y + v5.y) + (v6.y + v7.y));
    }
    for (; e < re; e++) {
        float2 v = __half22float2(in2[g_srcs[e] * 32 + lane]);
        acc.x += v.x; acc.y += v.y;
    }
    float iv = g_inv[warp];
    ((float2*)g_aggr)[warp * 32 + lane] = make_float2(acc.x * iv, acc.y * iv);
}

// ---------------- fused dual GEMM + bias + relu ---------------------------
// pass0 = aggr(fp32) @ Wl^T, pass1 = in(fp32) @ Wr^T; fp32 accumulate.
// Also emits half copy of the (post-relu) output for the next gather.
#define LIN_TPB 128
__global__ void __launch_bounds__(LIN_TPB)
k_linear(int in_sel, int out_sel, int outh_sel, const float* __restrict__ x,
         const float* __restrict__ Wl, const float* __restrict__ Wr,
         const float* __restrict__ bias, int do_relu) {
    __shared__ float wT[2][64 * 64];     // [pass][k*64 + j]
    __shared__ float sV[32 * 65];
    const float* in = sel_in(in_sel, x);
    float* out = sel_out(out_sel);
    __half2* outh = outh_sel == 1 ? (__half2*)g_hh0
                  : outh_sel == 2 ? (__half2*)g_hh1 : (__half2*)0;
    int t = threadIdx.x;
    for (int idx = t; idx < 4096; idx += LIN_TPB) {
        int j = idx >> 6, k = idx & 63;
        wT[0][k * 64 + j] = Wl[idx];
        wT[1][k * 64 + j] = Wr[idx];
    }
    int jt = t & 15;        // 16 j-groups of 4
    int nt = t >> 4;        // 8 node-groups of 4
    float4 bv = *(const float4*)&bias[jt * 4];
    __syncthreads();
    const int ntiles = N_NODES / 32;   // 2000
    for (int tile = blockIdx.x; tile < ntiles; tile += gridDim.x) {
        int base = tile * 32 * 64;
        float acc[4][4];
        #pragma unroll
        for (int i = 0; i < 4; i++) {
            acc[i][0] = bv.x; acc[i][1] = bv.y; acc[i][2] = bv.z; acc[i][3] = bv.w;
        }
        #pragma unroll
        for (int p = 0; p < 2; p++) {
            const float* src = p ? (in + base) : (g_aggr + base);
            for (int idx = t; idx < 2048; idx += LIN_TPB)
                sV[(idx >> 6) * 65 + (idx & 63)] = src[idx];
            __syncthreads();
            const float* wp = wT[p];
            int r = nt * 4 * 65;
            #pragma unroll 16
            for (int k = 0; k < 64; k++) {
                float4 w4 = *(const float4*)&wp[k * 64 + jt * 4];
                #pragma unroll
                for (int i = 0; i < 4; i++) {
                    float v = sV[r + i * 65 + k];
                    acc[i][0] += v * w4.x;
                    acc[i][1] += v * w4.y;
                    acc[i][2] += v * w4.z;
                    acc[i][3] += v * w4.w;
                }
            }
            __syncthreads();
        }
        #pragma unroll
        for (int i = 0; i < 4; i++) {
            float4 o = make_float4(acc[i][0], acc[i][1], acc[i][2], acc[i][3]);
            if (do_relu) {
                o.x = fmaxf(o.x, 0.f); o.y = fmaxf(o.y, 0.f);
                o.z = fmaxf(o.z, 0.f); o.w = fmaxf(o.w, 0.f);
            }
            int row = tile * 32 + nt * 4 + i;
            *(float4*)&out[row * 64 + jt * 4] = o;
            if (outh) {
                outh[row * 32 + jt * 2]     = __floats2half2_rn(o.x, o.y);
                outh[row * 32 + jt * 2 + 1] = __floats2half2_rn(o.z, o.w);
            }
        }
    }
}

// ---------------- final layer: project to 2 dims, THEN aggregate ----------
__global__ void k_project(const float* __restrict__ Wl_out,
                          const float* __restrict__ Wr_out,
                          const void* __restrict__ batch) {
    __shared__ float sp[N_GRAPHS * 2];
    for (int i = threadIdx.x; i < N_GRAPHS * 2; i += blockDim.x) sp[i] = 0.f;
    __syncthreads();
    int warp = (blockIdx.x * blockDim.x + threadIdx.x) >> 5;
    int lane = threadIdx.x & 31;
    if (warp < N_NODES) {
        float2 h   = ((const float2*)g_h0)[warp * 32 + lane];
        float2 wl0 = ((const float2*)Wl_out)[lane];
        float2 wl1 = ((const float2*)Wl_out)[32 + lane];
        float2 wr0 = ((const float2*)Wr_out)[lane];
        float2 wr1 = ((const float2*)Wr_out)[32 + lane];
        float y0 = h.x * wl0.x + h.y * wl0.y;
        float y1 = h.x * wl1.x + h.y * wl1.y;
        float z0 = h.x * wr0.x + h.y * wr0.y;
        float z1 = h.x * wr1.x + h.y * wr1.y;
        #pragma unroll
        for (int off = 16; off > 0; off >>= 1) {
            y0 += __shfl_xor_sync(0xFFFFFFFFu, y0, off);
            y1 += __shfl_xor_sync(0xFFFFFFFFu, y1, off);
            z0 += __shfl_xor_sync(0xFFFFFFFFu, z0, off);
            z1 += __shfl_xor_sync(0xFFFFFFFFu, z1, off);
        }
        if (lane == 0) {
            ((float2*)g_y)[warp] = make_float2(y0, y1);
            int g = load_idx(batch, warp);
            atomicAdd(&sp[g * 2 + 0], z0);
            atomicAdd(&sp[g * 2 + 1], z1);
        }
    }
    __syncthreads();
    for (int i = threadIdx.x; i < N_GRAPHS * 2; i += blockDim.x)
        if (sp[i] != 0.f) atomicAdd(&g_pool[i], sp[i]);
}

// gather 2-dim y over edges; thread per node; smem-accumulated pooling
__global__ void k_gather2(const void* __restrict__ batch) {
    __shared__ float sp[N_GRAPHS * 2];
    for (int i = threadIdx.x; i < N_GRAPHS * 2; i += blockDim.x) sp[i] = 0.f;
    __syncthreads();
    int n = blockIdx.x * blockDim.x + threadIdx.x;
    if (n < N_NODES) {
        int rs = g_rowptr[n], re = g_rowptr[n + 1];
        const float2* y2 = (const float2*)g_y;
        float a0 = 0.f, a1 = 0.f, b0 = 0.f, b1 = 0.f;
        int e = rs;
        for (; e + 4 <= re; e += 4) {
            float2 v0 = y2[g_srcs[e]];
            float2 v1 = y2[g_srcs[e + 1]];
            float2 v2 = y2[g_srcs[e + 2]];
            float2 v3 = y2[g_srcs[e + 3]];
            a0 += v0.x + v1.x; b0 += v2.x + v3.x;
            a1 += v0.y + v1.y; b1 += v2.y + v3.y;
        }
        for (; e < re; e++) {
            float2 v = y2[g_srcs[e]];
            a0 += v.x; a1 += v.y;
        }
        float iv = g_inv[n];
        int g = load_idx(batch, n);
        atomicAdd(&sp[g * 2 + 0], (a0 + b0) * iv);
        atomicAdd(&sp[g * 2 + 1], (a1 + b1) * iv);
    }
    __syncthreads();
    for (int i = threadIdx.x; i < N_GRAPHS * 2; i += blockDim.x)
        if (sp[i] != 0.f) atomicAdd(&g_pool[i], sp[i]);
}

__global__ void k_pool_out(const float* __restrict__ b_out, float* __restrict__ out) {
    int i = threadIdx.x;
    if (i >= N_GRAPHS * 2) return;
    int g = i >> 1;
    int c = g_gcnt[g];
    out[i] = (c > 0 ? g_pool[i] / (float)c : 0.f) + b_out[i & 1];
}

// ---------------- launch ---------------------------------------------------
extern "C" void kernel_launch(void* const* d_in, const int* in_sizes, int n_in,
                              void* d_out, int out_size) {
    const float* x      = (const float*)d_in[0];
    const void*  edges  = d_in[1];
    const void*  batch  = d_in[2];
    const float* Wl     = (const float*)d_in[3];
    const float* Wr     = (const float*)d_in[4];
    const float* b      = (const float*)d_in[5];
    const float* Wl_out = (const float*)d_in[6];
    const float* Wr_out = (const float*)d_in[7];
    const float* b_out  = (const float*)d_in[8];
    float* out = (float*)d_out;
    int E = in_sizes[1] / 2;

    int nb_nodes = (N_NODES + 255) / 256;     // 250
    int nb_edges = (E + 255) / 256;
    int nb_warps = N_NODES / 8;               // 8000

    k_detect<<<1, 32>>>(edges);
    k_zero<<<nb_nodes, 256>>>();
    k_tohalf<<<(N_NODES * D / 4 + 255) / 256, 256>>>(x);
    k_count<<<nb_edges, 256>>>(edges, E);
    k_scan1<<<125, 512>>>();
    k_scan2<<<1, 128>>>();
    k_scan3<<<125, 512>>>(E, batch);
    k_fill<<<nb_edges, 256>>>(edges, E);

    // layer 0: gather g_xh -> linear(x fp32) -> g_h0 + g_hh0
    k_aggregate<<<nb_warps, 256>>>(0);
    k_linear<<<740, LIN_TPB>>>(0, 1, 1, x, Wl, Wr, b, 1);
    // layer 1: gather g_hh0 -> linear(g_h0) -> g_h1 + g_hh1
    k_aggregate<<<nb_warps, 256>>>(1);
    k_linear<<<740, LIN_TPB>>>(1, 2, 2, x, Wl + 4096, Wr + 4096, b + 64, 1);
    // layer 2: gather g_hh1 -> linear(g_h1) -> g_h0 (fp32 only)
    k_aggregate<<<nb_warps, 256>>>(2);
    k_linear<<<740, LIN_TPB>>>(2, 1, 0, x, Wl + 8192, Wr + 8192, b + 128, 1);
    // final layer: project h to 2 dims, gather over edges, pool
    k_project<<<nb_warps, 256>>>(Wl_out, Wr_out, batch);
    k_gather2<<<nb_nodes, 256>>>(batch);
    k_pool_out<<<1, 256>>>(b_out, out);
}

// round 4
// speedup vs baseline: 1.6642x; 1.6642x over previous
#include <cuda_runtime.h>
#include <cuda_fp16.h>
#include <cstdint>

#define N_NODES 64000
#define N_GRAPHS 128
#define D 64
#define MAX_E 1024000

// ---------------- scratch (device globals; no allocation allowed) ----------
__device__ __half g_xh[N_NODES * D];       // fp16 feature tables
__device__ __half g_hh0[N_NODES * D];
__device__ __half g_hh1[N_NODES * D];
__device__ __half g_aggr_h[N_NODES * D];   // fp16 aggregated features
__device__ __half g_wh[3 * 128 * 64];      // concat [Wl^T ; Wr^T] per layer, k-major
__device__ float  g_y[N_NODES * 2];
__device__ int    g_deg[N_NODES];
__device__ int    g_rowptr[N_NODES + 1];
__device__ int    g_pos[N_NODES];
__device__ int    g_srcs[MAX_E];
__device__ float  g_inv[N_NODES];
__device__ float  g_pool[N_GRAPHS * 2];
__device__ int    g_gcnt[N_GRAPHS];
__device__ int    g_bsums[128];
__device__ int    g_is64;

__device__ __forceinline__ const __half2* sel_h(int s) {
    return (const __half2*)(s == 0 ? g_xh : (s == 1 ? g_hh0 : g_hh1));
}
__device__ __forceinline__ int load_idx(const void* p, int i) {
    return g_is64 ? (int)((const long long*)p)[i] : ((const int*)p)[i];
}
__device__ __forceinline__ uint32_t smem_u32(const void* p) {
    return (uint32_t)__cvta_generic_to_shared(p);
}

// ---------------- index dtype probe --------------------------------------
__global__ void k_detect(const void* edges) {
    if (threadIdx.x == 0 && blockIdx.x == 0) {
        const long long* p = (const long long*)edges;
        int ok = 1;
        for (int i = 0; i < 16; i++) {
            long long v = p[i];
            if (v < 0 || v >= N_NODES) ok = 0;
        }
        g_is64 = ok;
    }
}

__global__ void k_zero() {
    int i = blockIdx.x * blockDim.x + threadIdx.x;
    if (i < N_NODES) g_deg[i] = 0;
    if (i < N_GRAPHS * 2) g_pool[i] = 0.f;
    if (i < N_GRAPHS) g_gcnt[i] = 0;
}

// convert x (fp32) -> g_xh (half)
__global__ void k_tohalf(const float* __restrict__ x) {
    int i = blockIdx.x * blockDim.x + threadIdx.x;
    if (i >= N_NODES * D / 4) return;
    float4 v = ((const float4*)x)[i];
    __half2* o = (__half2*)g_xh;
    o[i * 2]     = __floats2half2_rn(v.x, v.y);
    o[i * 2 + 1] = __floats2half2_rn(v.z, v.w);
}

// weights -> fp16, concat layout: g_wh[l][k*64+j], k<64 from Wl[j][k], else Wr
__global__ void k_wconv(const float* __restrict__ Wl, const float* __restrict__ Wr) {
    int i = blockIdx.x * blockDim.x + threadIdx.x;
    if (i >= 3 * 128 * 64) return;
    int l = i >> 13;          // /8192
    int r = i & 8191;
    int k = r >> 6, j = r & 63;
    float v = (k < 64) ? Wl[l * 4096 + j * 64 + k] : Wr[l * 4096 + j * 64 + (k - 64)];
    g_wh[i] = __float2half_rn(v);
}

__global__ void k_count(const void* edges, int E) {
    int e = blockIdx.x * blockDim.x + threadIdx.x;
    if (e >= E) return;
    atomicAdd(&g_deg[load_idx(edges, E + e)], 1);
}

// ---------------- 3-kernel exclusive scan of degrees ----------------------
__global__ void k_scan1() {
    __shared__ int s[512];
    int t = threadIdx.x;
    int i = blockIdx.x * 512 + t;          // 125 * 512 = 64000 exactly
    int d = g_deg[i];
    s[t] = d;
    __syncthreads();
    for (int off = 1; off < 512; off <<= 1) {
        int v = (t >= off) ? s[t - off] : 0;
        __syncthreads();
        s[t] += v;
        __syncthreads();
    }
    g_rowptr[i] = s[t] - d;
    if (t == 511) g_bsums[blockIdx.x] = s[511];
}

__global__ void k_scan2() {
    __shared__ int s[128];
    int t = threadIdx.x;
    int v = (t < 125) ? g_bsums[t] : 0;
    s[t] = v;
    __syncthreads();
    for (int off = 1; off < 128; off <<= 1) {
        int u = (t >= off) ? s[t - off] : 0;
        __syncthreads();
        s[t] += u;
        __syncthreads();
    }
    g_bsums[t] = s[t] - v;
}

__global__ void k_scan3(int E, const void* __restrict__ batch) {
    __shared__ int h[N_GRAPHS];
    for (int i = threadIdx.x; i < N_GRAPHS; i += blockDim.x) h[i] = 0;
    __syncthreads();
    int t = threadIdx.x;
    int i = blockIdx.x * 512 + t;
    int rp = g_rowptr[i] + g_bsums[blockIdx.x];
    g_rowptr[i] = rp;
    g_pos[i] = rp;
    int d = g_deg[i];
    g_inv[i] = d > 0 ? 1.0f / (float)d : 0.f;
    if (i == 0) g_rowptr[N_NODES] = E;
    atomicAdd(&h[load_idx(batch, i)], 1);
    __syncthreads();
    for (int g = threadIdx.x; g < N_GRAPHS; g += blockDim.x)
        if (h[g]) atomicAdd(&g_gcnt[g], h[g]);
}

__global__ void k_fill(const void* edges, int E) {
    int e = blockIdx.x * blockDim.x + threadIdx.x;
    if (e >= E) return;
    int src = load_idx(edges, e);
    int dst = load_idx(edges, E + e);
    int pidx = atomicAdd(&g_pos[dst], 1);
    g_srcs[pidx] = src;
}

// ---------------- mean aggregation: warp per node, half2 lanes ------------
__global__ void k_aggregate(int in_sel) {
    const __half2* __restrict__ in2 = sel_h(in_sel);
    int warp = (blockIdx.x * blockDim.x + threadIdx.x) >> 5;
    int lane = threadIdx.x & 31;
    if (warp >= N_NODES) return;
    int rs = g_rowptr[warp], re = g_rowptr[warp + 1];
    float2 acc = make_float2(0.f, 0.f);
    int e = rs;
    for (; e + 8 <= re; e += 8) {
        int s0 = g_srcs[e],     s1 = g_srcs[e + 1], s2 = g_srcs[e + 2], s3 = g_srcs[e + 3];
        int s4 = g_srcs[e + 4], s5 = g_srcs[e + 5], s6 = g_srcs[e + 6], s7 = g_srcs[e + 7];
        float2 v0 = __half22float2(in2[s0 * 32 + lane]);
        float2 v1 = __half22float2(in2[s1 * 32 + lane]);
        float2 v2 = __half22float2(in2[s2 * 32 + lane]);
        float2 v3 = __half22float2(in2[s3 * 32 + lane]);
        float2 v4 = __half22float2(in2[s4 * 32 + lane]);
        float2 v5 = __half22float2(in2[s5 * 32 + lane]);
        float2 v6 = __half22float2(in2[s6 * 32 + lane]);
        float2 v7 = __half22float2(in2[s7 * 32 + lane]);
        acc.x += ((v0.x + v1.x) + (v2.x + v3.x)) + ((v4.x + v5.x) + (v6.x + v7.x));
        acc.y += ((v0.y + v1.y) + (v2.y + v3.y)) + ((v4.y + v5.y) + (v6.y + v7.y));
    }
    for (; e < re; e++) {
        float2 v = __half22float2(in2[g_srcs[e] * 32 + lane]);
        acc.x += v.x; acc.y += v.y;
    }
    float iv = g_inv[warp];
    ((__half2*)g_aggr_h)[warp * 32 + lane] = __floats2half2_rn(acc.x * iv, acc.y * iv);
}

// ---------------- HMMA dual GEMM + bias + relu ----------------------------
// out[n][j] = relu( A[n][:] @ B[:][j] + bias[j] ),
//   A = [aggr_h | in_h] (n x 128 fp16), B = g_wh[layer] (128 x 64 fp16 k-major)
// block = 256 thr (8 warps); warp w owns j-tile [w*8, w*8+8); B frags in regs.
// Tile = 32 nodes; m16n8k16 mma, fp32 accum.
#define LWS_A 136   // sA row stride in halves (272 B: +16B pad -> conflict-free ldmatrix)
#define LWS_W 72    // wS row stride in halves (144 B pad)
__global__ void __launch_bounds__(256)
k_linear_hmma(int in_sel, int out_sel, int layer, const float* __restrict__ bias) {
    __shared__ __half wS[128 * LWS_W];
    __shared__ __half sA[32 * LWS_A];
    const __half* in = (const __half*)sel_h(in_sel);
    __half2* out = (__half2*)(out_sel == 1 ? g_hh0 : g_hh1);
    int t = threadIdx.x;
    int lane = t & 31;
    int w = t >> 5;           // warp id = j-tile

    // stage weights (8192 halves) into padded smem
    {
        const __half2* src = (const __half2*)(g_wh + layer * 8192);
        for (int i = t; i < 4096; i += 256) {
            int k = i >> 5, jp = i & 31;
            *(__half2*)&wS[k * LWS_W + jp * 2] = src[i];
        }
    }
    __syncthreads();

    // preload B fragments: 8 k-steps, ldmatrix.x2.trans over 16x8 row-major tiles
    uint32_t B[8][2];
    #pragma unroll
    for (int ks = 0; ks < 8; ks++) {
        uint32_t addr = smem_u32(&wS[(ks * 16 + (lane & 15)) * LWS_W + w * 8]);
        asm volatile("ldmatrix.sync.aligned.m8n8.x2.trans.shared.b16 {%0,%1}, [%2];\n"
                     : "=r"(B[ks][0]), "=r"(B[ks][1]) : "r"(addr));
    }

    float2 b2 = *(const float2*)&bias[w * 8 + 2 * (lane & 3)];

    const int ntiles = N_NODES / 32;   // 2000
    for (int tile = blockIdx.x; tile < ntiles; tile += gridDim.x) {
        int base = tile * 32;
        // cooperative load of A tile: 32 rows x 128 halves (aggr | in)
        for (int c = t; c < 512; c += 256) {
            int row = c >> 4, c16 = c & 15;
            const __half* srcp = (c16 < 8)
                ? (g_aggr_h + (base + row) * 64 + c16 * 8)
                : (in       + (base + row) * 64 + (c16 - 8) * 8);
            *(uint4*)&sA[row * LWS_A + c16 * 8] = *(const uint4*)srcp;
        }
        __syncthreads();

        #pragma unroll
        for (int mt = 0; mt < 2; mt++) {
            float acc[4] = {b2.x, b2.y, b2.x, b2.y};
            #pragma unroll
            for (int ks = 0; ks < 8; ks++) {
                uint32_t a0, a1, a2, a3;
                uint32_t addr = smem_u32(&sA[(mt * 16 + (lane & 15)) * LWS_A
                                             + ks * 16 + (lane >> 4) * 8]);
                asm volatile("ldmatrix.sync.aligned.m8n8.x4.shared.b16 {%0,%1,%2,%3}, [%4];\n"
                             : "=r"(a0), "=r"(a1), "=r"(a2), "=r"(a3) : "r"(addr));
                asm volatile("mma.sync.aligned.m16n8k16.row.col.f32.f16.f16.f32 "
                             "{%0,%1,%2,%3}, {%4,%5,%6,%7}, {%8,%9}, {%0,%1,%2,%3};\n"
                             : "+f"(acc[0]), "+f"(acc[1]), "+f"(acc[2]), "+f"(acc[3])
                             : "r"(a0), "r"(a1), "r"(a2), "r"(a3),
                               "r"(B[ks][0]), "r"(B[ks][1]));
            }
            // epilogue: relu + half2 store. d0,d1 -> row lane/4; d2,d3 -> +8
            int row0 = base + mt * 16 + (lane >> 2);
            int colp = w * 4 + (lane & 3);           // half2 column index
            __half2 lo = __floats2half2_rn(fmaxf(acc[0], 0.f), fmaxf(acc[1], 0.f));
            __half2 hi = __floats2half2_rn(fmaxf(acc[2], 0.f), fmaxf(acc[3], 0.f));
            out[row0 * 32 + colp] = lo;
            out[(row0 + 8) * 32 + colp] = hi;
        }
        __syncthreads();
    }
}

// ---------------- final layer: project to 2 dims, THEN aggregate ----------
__global__ void k_project(const float* __restrict__ Wl_out,
                          const float* __restrict__ Wr_out,
                          const void* __restrict__ batch) {
    __shared__ float sp[N_GRAPHS * 2];
    for (int i = threadIdx.x; i < N_GRAPHS * 2; i += blockDim.x) sp[i] = 0.f;
    __syncthreads();
    int warp = (blockIdx.x * blockDim.x + threadIdx.x) >> 5;
    int lane = threadIdx.x & 31;
    if (warp < N_NODES) {
        float2 h   = __half22float2(((const __half2*)g_hh0)[warp * 32 + lane]);
        float2 wl0 = ((const float2*)Wl_out)[lane];
        float2 wl1 = ((const float2*)Wl_out)[32 + lane];
        float2 wr0 = ((const float2*)Wr_out)[lane];
        float2 wr1 = ((const float2*)Wr_out)[32 + lane];
        float y0 = h.x * wl0.x + h.y * wl0.y;
        float y1 = h.x * wl1.x + h.y * wl1.y;
        float z0 = h.x * wr0.x + h.y * wr0.y;
        float z1 = h.x * wr1.x + h.y * wr1.y;
        #pragma unroll
        for (int off = 16; off > 0; off >>= 1) {
            y0 += __shfl_xor_sync(0xFFFFFFFFu, y0, off);
            y1 += __shfl_xor_sync(0xFFFFFFFFu, y1, off);
            z0 += __shfl_xor_sync(0xFFFFFFFFu, z0, off);
            z1 += __shfl_xor_sync(0xFFFFFFFFu, z1, off);
        }
        if (lane == 0) {
            ((float2*)g_y)[warp] = make_float2(y0, y1);
            int g = load_idx(batch, warp);
            atomicAdd(&sp[g * 2 + 0], z0);
            atomicAdd(&sp[g * 2 + 1], z1);
        }
    }
    __syncthreads();
    for (int i = threadIdx.x; i < N_GRAPHS * 2; i += blockDim.x)
        if (sp[i] != 0.f) atomicAdd(&g_pool[i], sp[i]);
}

// gather 2-dim y over edges; thread per node; smem-accumulated pooling
__global__ void k_gather2(const void* __restrict__ batch) {
    __shared__ float sp[N_GRAPHS * 2];
    for (int i = threadIdx.x; i < N_GRAPHS * 2; i += blockDim.x) sp[i] = 0.f;
    __syncthreads();
    int n = blockIdx.x * blockDim.x + threadIdx.x;
    if (n < N_NODES) {
        int rs = g_rowptr[n], re = g_rowptr[n + 1];
        const float2* y2 = (const float2*)g_y;
        float a0 = 0.f, a1 = 0.f, b0 = 0.f, b1 = 0.f;
        int e = rs;
        for (; e + 4 <= re; e += 4) {
            float2 v0 = y2[g_srcs[e]];
            float2 v1 = y2[g_srcs[e + 1]];
            float2 v2 = y2[g_srcs[e + 2]];
            float2 v3 = y2[g_srcs[e + 3]];
            a0 += v0.x + v1.x; b0 += v2.x + v3.x;
            a1 += v0.y + v1.y; b1 += v2.y + v3.y;
        }
        for (; e < re; e++) {
            float2 v = y2[g_srcs[e]];
            a0 += v.x; a1 += v.y;
        }
        float iv = g_inv[n];
        int g = load_idx(batch, n);
        atomicAdd(&sp[g * 2 + 0], (a0 + b0) * iv);
        atomicAdd(&sp[g * 2 + 1], (a1 + b1) * iv);
    }
    __syncthreads();
    for (int i = threadIdx.x; i < N_GRAPHS * 2; i += blockDim.x)
        if (sp[i] != 0.f) atomicAdd(&g_pool[i], sp[i]);
}

__global__ void k_pool_out(const float* __restrict__ b_out, float* __restrict__ out) {
    int i = threadIdx.x;
    if (i >= N_GRAPHS * 2) return;
    int g = i >> 1;
    int c = g_gcnt[g];
    out[i] = (c > 0 ? g_pool[i] / (float)c : 0.f) + b_out[i & 1];
}

// ---------------- launch ---------------------------------------------------
extern "C" void kernel_launch(void* const* d_in, const int* in_sizes, int n_in,
                              void* d_out, int out_size) {
    const float* x      = (const float*)d_in[0];
    const void*  edges  = d_in[1];
    const void*  batch  = d_in[2];
    const float* Wl     = (const float*)d_in[3];
    const float* Wr     = (const float*)d_in[4];
    const float* b      = (const float*)d_in[5];
    const float* Wl_out = (const float*)d_in[6];
    const float* Wr_out = (const float*)d_in[7];
    const float* b_out  = (const float*)d_in[8];
    float* out = (float*)d_out;
    int E = in_sizes[1] / 2;

    int nb_nodes = (N_NODES + 255) / 256;
    int nb_edges = (E + 255) / 256;
    int nb_warps = N_NODES / 8;               // 8000

    k_detect<<<1, 32>>>(edges);
    k_zero<<<nb_nodes, 256>>>();
    k_tohalf<<<(N_NODES * D / 4 + 255) / 256, 256>>>(x);
    k_wconv<<<(3 * 128 * 64 + 255) / 256, 256>>>(Wl, Wr);
    k_count<<<nb_edges, 256>>>(edges, E);
    k_scan1<<<125, 512>>>();
    k_scan2<<<1, 128>>>();
    k_scan3<<<125, 512>>>(E, batch);
    k_fill<<<nb_edges, 256>>>(edges, E);

    // layer 0: gather g_xh -> aggr_h; GEMM([aggr|x_h] @ W0) -> g_hh0
    k_aggregate<<<nb_warps, 256>>>(0);
    k_linear_hmma<<<500, 256>>>(0, 1, 0, b);
    // layer 1: g_hh0 -> g_hh1
    k_aggregate<<<nb_warps, 256>>>(1);
    k_linear_hmma<<<500, 256>>>(1, 2, 1, b + 64);
    // layer 2: g_hh1 -> g_hh0
    k_aggregate<<<nb_warps, 256>>>(2);
    k_linear_hmma<<<500, 256>>>(2, 1, 2, b + 128);
    // final layer: project, gather 2-dim, pool
    k_project<<<nb_warps, 256>>>(Wl_out, Wr_out, batch);
    k_gather2<<<nb_nodes, 256>>>(batch);
    k_pool_out<<<1, 256>>>(b_out, out);
}

// round 5
// speedup vs baseline: 1.6848x; 1.0124x over previous
#include <cuda_runtime.h>
#include <cuda_fp16.h>
#include <cstdint>

#define N_NODES 64000
#define N_GRAPHS 128
#define D 64
#define MAX_E 1024000

// ---------------- scratch (device globals; no allocation allowed) ----------
__device__ __half g_xh[N_NODES * D];       // fp16 feature tables
__device__ __half g_hh0[N_NODES * D];
__device__ __half g_hh1[N_NODES * D];
__device__ __half g_aggr_h[N_NODES * D];   // fp16 aggregated features
__device__ __half g_wh[3 * 128 * 64];      // concat [Wl^T ; Wr^T] per layer, k-major
__device__ float  g_y[N_NODES * 2];
__device__ int    g_deg[N_NODES];
__device__ int    g_rowptr[N_NODES + 1];
__device__ int    g_pos[N_NODES];
__device__ int    g_srcs[MAX_E];
__device__ float  g_inv[N_NODES];
__device__ float  g_pool[N_GRAPHS * 2];
__device__ int    g_gcnt[N_GRAPHS];
__device__ int    g_bsums[128];
__device__ int    g_is64;

__device__ __forceinline__ const __half2* sel_h(int s) {
    return (const __half2*)(s == 0 ? g_xh : (s == 1 ? g_hh0 : g_hh1));
}
__device__ __forceinline__ int load_idx(const void* p, int i) {
    return g_is64 ? (int)((const long long*)p)[i] : ((const int*)p)[i];
}
__device__ __forceinline__ uint32_t smem_u32(const void* p) {
    return (uint32_t)__cvta_generic_to_shared(p);
}

// ---------------- fused prologue: detect + zero + tohalf + wconv ----------
__global__ void k_prologue(const void* edges, const float* __restrict__ x,
                           const float* __restrict__ Wl, const float* __restrict__ Wr) {
    int i = blockIdx.x * blockDim.x + threadIdx.x;
    if (i == 0) {
        const long long* p = (const long long*)edges;
        int ok = 1;
        for (int q = 0; q < 16; q++) {
            long long v = p[q];
            if (v < 0 || v >= N_NODES) ok = 0;
        }
        g_is64 = ok;
    }
    if (i < N_NODES) g_deg[i] = 0;
    if (i < N_GRAPHS * 2) g_pool[i] = 0.f;
    if (i < N_GRAPHS) g_gcnt[i] = 0;
    if (i < N_NODES * D / 4) {
        float4 v = ((const float4*)x)[i];
        __half2* o = (__half2*)g_xh;
        o[i * 2]     = __floats2half2_rn(v.x, v.y);
        o[i * 2 + 1] = __floats2half2_rn(v.z, v.w);
    }
    if (i < 3 * 128 * 64) {
        int l = i >> 13;
        int r = i & 8191;
        int k = r >> 6, j = r & 63;
        float v = (k < 64) ? Wl[l * 4096 + j * 64 + k] : Wr[l * 4096 + j * 64 + (k - 64)];
        g_wh[i] = __float2half_rn(v);
    }
}

// 2 edges per thread, 128-bit index loads
__global__ void k_count(const void* edges, int E) {
    int i = blockIdx.x * blockDim.x + threadIdx.x;
    int e = i * 2;
    if (e >= E) return;
    int d0, d1;
    if (g_is64) {
        longlong2 d = *(const longlong2*)((const long long*)edges + E + e);
        d0 = (int)d.x; d1 = (int)d.y;
    } else {
        int2 d = *(const int2*)((const int*)edges + E + e);
        d0 = d.x; d1 = d.y;
    }
    atomicAdd(&g_deg[d0], 1);
    if (e + 1 < E) atomicAdd(&g_deg[d1], 1);
}

// ---------------- 3-kernel exclusive scan of degrees ----------------------
__global__ void k_scan1() {
    __shared__ int s[512];
    int t = threadIdx.x;
    int i = blockIdx.x * 512 + t;          // 125 * 512 = 64000 exactly
    int d = g_deg[i];
    s[t] = d;
    __syncthreads();
    for (int off = 1; off < 512; off <<= 1) {
        int v = (t >= off) ? s[t - off] : 0;
        __syncthreads();
        s[t] += v;
        __syncthreads();
    }
    g_rowptr[i] = s[t] - d;
    if (t == 511) g_bsums[blockIdx.x] = s[511];
}

__global__ void k_scan2() {
    __shared__ int s[128];
    int t = threadIdx.x;
    int v = (t < 125) ? g_bsums[t] : 0;
    s[t] = v;
    __syncthreads();
    for (int off = 1; off < 128; off <<= 1) {
        int u = (t >= off) ? s[t - off] : 0;
        __syncthreads();
        s[t] += u;
        __syncthreads();
    }
    g_bsums[t] = s[t] - v;
}

__global__ void k_scan3(int E, const void* __restrict__ batch) {
    __shared__ int h[N_GRAPHS];
    for (int i = threadIdx.x; i < N_GRAPHS; i += blockDim.x) h[i] = 0;
    __syncthreads();
    int t = threadIdx.x;
    int i = blockIdx.x * 512 + t;
    int rp = g_rowptr[i] + g_bsums[blockIdx.x];
    g_rowptr[i] = rp;
    g_pos[i] = rp;
    int d = g_deg[i];
    g_inv[i] = d > 0 ? 1.0f / (float)d : 0.f;
    if (i == 0) g_rowptr[N_NODES] = E;
    atomicAdd(&h[load_idx(batch, i)], 1);
    __syncthreads();
    for (int g = threadIdx.x; g < N_GRAPHS; g += blockDim.x)
        if (h[g]) atomicAdd(&g_gcnt[g], h[g]);
}

// 2 edges per thread, 128-bit index loads
__global__ void k_fill(const void* edges, int E) {
    int i = blockIdx.x * blockDim.x + threadIdx.x;
    int e = i * 2;
    if (e >= E) return;
    int s0, s1, d0, d1;
    if (g_is64) {
        longlong2 s = *(const longlong2*)((const long long*)edges + e);
        longlong2 d = *(const longlong2*)((const long long*)edges + E + e);
        s0 = (int)s.x; s1 = (int)s.y; d0 = (int)d.x; d1 = (int)d.y;
    } else {
        int2 s = *(const int2*)((const int*)edges + e);
        int2 d = *(const int2*)((const int*)edges + E + e);
        s0 = s.x; s1 = s.y; d0 = d.x; d1 = d.y;
    }
    g_srcs[atomicAdd(&g_pos[d0], 1)] = s0;
    if (e + 1 < E) g_srcs[atomicAdd(&g_pos[d1], 1)] = s1;
}

// ---------------- mean aggregation: warp per node, uint4 lanes ------------
// 8 lanes cover one 128B row; 4 edge-groups per warp; unroll 16 edges/iter
// -> 16 cache lines outstanding per warp (2x the half2 version's MLP).
__device__ __forceinline__ void add8(float* acc, uint4 v) {
    float2 a = __half22float2(*(__half2*)&v.x);
    float2 b = __half22float2(*(__half2*)&v.y);
    float2 c = __half22float2(*(__half2*)&v.z);
    float2 d = __half22float2(*(__half2*)&v.w);
    acc[0] += a.x; acc[1] += a.y; acc[2] += b.x; acc[3] += b.y;
    acc[4] += c.x; acc[5] += c.y; acc[6] += d.x; acc[7] += d.y;
}

__global__ void k_aggregate(int in_sel) {
    const __half* __restrict__ in = (const __half*)sel_h(in_sel);
    int warp = (blockIdx.x * blockDim.x + threadIdx.x) >> 5;
    int lane = threadIdx.x & 31;
    if (warp >= N_NODES) return;
    int g = lane >> 3, r = lane & 7;
    int rs = g_rowptr[warp], re = g_rowptr[warp + 1];
    float acc[8] = {0.f, 0.f, 0.f, 0.f, 0.f, 0.f, 0.f, 0.f};
    int e = rs;
    for (; e + 16 <= re; e += 16) {
        int s0 = g_srcs[e + g];
        int s1 = g_srcs[e + 4 + g];
        int s2 = g_srcs[e + 8 + g];
        int s3 = g_srcs[e + 12 + g];
        uint4 v0 = *(const uint4*)(in + s0 * 64 + r * 8);
        uint4 v1 = *(const uint4*)(in + s1 * 64 + r * 8);
        uint4 v2 = *(const uint4*)(in + s2 * 64 + r * 8);
        uint4 v3 = *(const uint4*)(in + s3 * 64 + r * 8);
        add8(acc, v0); add8(acc, v1); add8(acc, v2); add8(acc, v3);
    }
    for (; e < re; e += 4) {
        if (e + g < re) {
            int s = g_srcs[e + g];
            uint4 v = *(const uint4*)(in + s * 64 + r * 8);
            add8(acc, v);
        }
    }
    // combine the 4 edge groups (lanes xor 8, xor 16)
    #pragma unroll
    for (int i = 0; i < 8; i++) {
        acc[i] += __shfl_xor_sync(0xFFFFFFFFu, acc[i], 8);
        acc[i] += __shfl_xor_sync(0xFFFFFFFFu, acc[i], 16);
    }
    if (g == 0) {
        float iv = g_inv[warp];
        uint4 o;
        *(__half2*)&o.x = __floats2half2_rn(acc[0] * iv, acc[1] * iv);
        *(__half2*)&o.y = __floats2half2_rn(acc[2] * iv, acc[3] * iv);
        *(__half2*)&o.z = __floats2half2_rn(acc[4] * iv, acc[5] * iv);
        *(__half2*)&o.w = __floats2half2_rn(acc[6] * iv, acc[7] * iv);
        *(uint4*)(g_aggr_h + warp * 64 + r * 8) = o;
    }
}

// ---------------- HMMA dual GEMM + bias + relu ----------------------------
#define LWS_A 136
#define LWS_W 72
__global__ void __launch_bounds__(256)
k_linear_hmma(int in_sel, int out_sel, int layer, const float* __restrict__ bias) {
    __shared__ __half wS[128 * LWS_W];
    __shared__ __half sA[32 * LWS_A];
    const __half* in = (const __half*)sel_h(in_sel);
    __half2* out = (__half2*)(out_sel == 1 ? g_hh0 : g_hh1);
    int t = threadIdx.x;
    int lane = t & 31;
    int w = t >> 5;

    {
        const __half2* src = (const __half2*)(g_wh + layer * 8192);
        for (int i = t; i < 4096; i += 256) {
            int k = i >> 5, jp = i & 31;
            *(__half2*)&wS[k * LWS_W + jp * 2] = src[i];
        }
    }
    __syncthreads();

    uint32_t B[8][2];
    #pragma unroll
    for (int ks = 0; ks < 8; ks++) {
        uint32_t addr = smem_u32(&wS[(ks * 16 + (lane & 15)) * LWS_W + w * 8]);
        asm volatile("ldmatrix.sync.aligned.m8n8.x2.trans.shared.b16 {%0,%1}, [%2];\n"
                     : "=r"(B[ks][0]), "=r"(B[ks][1]) : "r"(addr));
    }

    float2 b2 = *(const float2*)&bias[w * 8 + 2 * (lane & 3)];

    const int ntiles = N_NODES / 32;
    for (int tile = blockIdx.x; tile < ntiles; tile += gridDim.x) {
        int base = tile * 32;
        for (int c = t; c < 512; c += 256) {
            int row = c >> 4, c16 = c & 15;
            const __half* srcp = (c16 < 8)
                ? (g_aggr_h + (base + row) * 64 + c16 * 8)
                : (in       + (base + row) * 64 + (c16 - 8) * 8);
            *(uint4*)&sA[row * LWS_A + c16 * 8] = *(const uint4*)srcp;
        }
        __syncthreads();

        #pragma unroll
        for (int mt = 0; mt < 2; mt++) {
            float acc[4] = {b2.x, b2.y, b2.x, b2.y};
            #pragma unroll
            for (int ks = 0; ks < 8; ks++) {
                uint32_t a0, a1, a2, a3;
                uint32_t addr = smem_u32(&sA[(mt * 16 + (lane & 15)) * LWS_A
                                             + ks * 16 + (lane >> 4) * 8]);
                asm volatile("ldmatrix.sync.aligned.m8n8.x4.shared.b16 {%0,%1,%2,%3}, [%4];\n"
                             : "=r"(a0), "=r"(a1), "=r"(a2), "=r"(a3) : "r"(addr));
                asm volatile("mma.sync.aligned.m16n8k16.row.col.f32.f16.f16.f32 "
                             "{%0,%1,%2,%3}, {%4,%5,%6,%7}, {%8,%9}, {%0,%1,%2,%3};\n"
                             : "+f"(acc[0]), "+f"(acc[1]), "+f"(acc[2]), "+f"(acc[3])
                             : "r"(a0), "r"(a1), "r"(a2), "r"(a3),
                               "r"(B[ks][0]), "r"(B[ks][1]));
            }
            int row0 = base + mt * 16 + (lane >> 2);
            int colp = w * 4 + (lane & 3);
            __half2 lo = __floats2half2_rn(fmaxf(acc[0], 0.f), fmaxf(acc[1], 0.f));
            __half2 hi = __floats2half2_rn(fmaxf(acc[2], 0.f), fmaxf(acc[3], 0.f));
            out[row0 * 32 + colp] = lo;
            out[(row0 + 8) * 32 + colp] = hi;
        }
        __syncthreads();
    }
}

// ---------------- final layer: project to 2 dims, THEN aggregate ----------
__global__ void k_project(const float* __restrict__ Wl_out,
                          const float* __restrict__ Wr_out,
                          const void* __restrict__ batch) {
    __shared__ float sp[N_GRAPHS * 2];
    for (int i = threadIdx.x; i < N_GRAPHS * 2; i += blockDim.x) sp[i] = 0.f;
    __syncthreads();
    int warp = (blockIdx.x * blockDim.x + threadIdx.x) >> 5;
    int lane = threadIdx.x & 31;
    if (warp < N_NODES) {
        float2 h   = __half22float2(((const __half2*)g_hh0)[warp * 32 + lane]);
        float2 wl0 = ((const float2*)Wl_out)[lane];
        float2 wl1 = ((const float2*)Wl_out)[32 + lane];
        float2 wr0 = ((const float2*)Wr_out)[lane];
        float2 wr1 = ((const float2*)Wr_out)[32 + lane];
        float y0 = h.x * wl0.x + h.y * wl0.y;
        float y1 = h.x * wl1.x + h.y * wl1.y;
        float z0 = h.x * wr0.x + h.y * wr0.y;
        float z1 = h.x * wr1.x + h.y * wr1.y;
        #pragma unroll
        for (int off = 16; off > 0; off >>= 1) {
            y0 += __shfl_xor_sync(0xFFFFFFFFu, y0, off);
            y1 += __shfl_xor_sync(0xFFFFFFFFu, y1, off);
            z0 += __shfl_xor_sync(0xFFFFFFFFu, z0, off);
            z1 += __shfl_xor_sync(0xFFFFFFFFu, z1, off);
        }
        if (lane == 0) {
            ((float2*)g_y)[warp] = make_float2(y0, y1);
            int g = load_idx(batch, warp);
            atomicAdd(&sp[g * 2 + 0], z0);
            atomicAdd(&sp[g * 2 + 1], z1);
        }
    }
    __syncthreads();
    for (int i = threadIdx.x; i < N_GRAPHS * 2; i += blockDim.x)
        if (sp[i] != 0.f) atomicAdd(&g_pool[i], sp[i]);
}

__global__ void k_gather2(const void* __restrict__ batch) {
    __shared__ float sp[N_GRAPHS * 2];
    for (int i = threadIdx.x; i < N_GRAPHS * 2; i += blockDim.x) sp[i] = 0.f;
    __syncthreads();
    int n = blockIdx.x * blockDim.x + threadIdx.x;
    if (n < N_NODES) {
        int rs = g_rowptr[n], re = g_rowptr[n + 1];
        const float2* y2 = (const float2*)g_y;
        float a0 = 0.f, a1 = 0.f, b0 = 0.f, b1 = 0.f;
        int e = rs;
        for (; e + 4 <= re; e += 4) {
            float2 v0 = y2[g_srcs[e]];
            float2 v1 = y2[g_srcs[e + 1]];
            float2 v2 = y2[g_srcs[e + 2]];
            float2 v3 = y2[g_srcs[e + 3]];
            a0 += v0.x + v1.x; b0 += v2.x + v3.x;
            a1 += v0.y + v1.y; b1 += v2.y + v3.y;
        }
        for (; e < re; e++) {
            float2 v = y2[g_srcs[e]];
            a0 += v.x; a1 += v.y;
        }
        float iv = g_inv[n];
        int g = load_idx(batch, n);
        atomicAdd(&sp[g * 2 + 0], (a0 + b0) * iv);
        atomicAdd(&sp[g * 2 + 1], (a1 + b1) * iv);
    }
    __syncthreads();
    for (int i = threadIdx.x; i < N_GRAPHS * 2; i += blockDim.x)
        if (sp[i] != 0.f) atomicAdd(&g_pool[i], sp[i]);
}

__global__ void k_pool_out(const float* __restrict__ b_out, float* __restrict__ out) {
    int i = threadIdx.x;
    if (i >= N_GRAPHS * 2) return;
    int g = i >> 1;
    int c = g_gcnt[g];
    out[i] = (c > 0 ? g_pool[i] / (float)c : 0.f) + b_out[i & 1];
}

// ---------------- launch ---------------------------------------------------
extern "C" void kernel_launch(void* const* d_in, const int* in_sizes, int n_in,
                              void* d_out, int out_size) {
    const float* x      = (const float*)d_in[0];
    const void*  edges  = d_in[1];
    const void*  batch  = d_in[2];
    const float* Wl     = (const float*)d_in[3];
    const float* Wr     = (const float*)d_in[4];
    const float* b      = (const float*)d_in[5];
    const float* Wl_out = (const float*)d_in[6];
    const float* Wr_out = (const float*)d_in[7];
    const float* b_out  = (const float*)d_in[8];
    float* out = (float*)d_out;
    int E = in_sizes[1] / 2;

    int nb_nodes = (N_NODES + 255) / 256;
    int nb_pairs = (E / 2 + 255) / 256;       // 2 edges per thread
    int nb_warps = N_NODES / 8;               // 8000

    k_prologue<<<(N_NODES * D / 4 + 255) / 256, 256>>>(edges, x, Wl, Wr);
    k_count<<<nb_pairs, 256>>>(edges, E);
    k_scan1<<<125, 512>>>();
    k_scan2<<<1, 128>>>();
    k_scan3<<<125, 512>>>(E, batch);
    k_fill<<<nb_pairs, 256>>>(edges, E);

    // layer 0: gather g_xh -> aggr_h; GEMM([aggr|x_h] @ W0) -> g_hh0
    k_aggregate<<<nb_warps, 256>>>(0);
    k_linear_hmma<<<500, 256>>>(0, 1, 0, b);
    // layer 1: g_hh0 -> g_hh1
    k_aggregate<<<nb_warps, 256>>>(1);
    k_linear_hmma<<<500, 256>>>(1, 2, 1, b + 64);
    // layer 2: g_hh1 -> g_hh0
    k_aggregate<<<nb_warps, 256>>>(2);
    k_linear_hmma<<<500, 256>>>(2, 1, 2, b + 128);
    // final layer: project, gather 2-dim, pool
    k_project<<<nb_warps, 256>>>(Wl_out, Wr_out, batch);
    k_gather2<<<nb_nodes, 256>>>(batch);
    k_pool_out<<<1, 256>>>(b_out, out);
}